// round 16
// baseline (speedup 1.0000x reference)
#include <cuda_runtime.h>
#include <cuda_bf16.h>
#include <cuda_fp16.h>
#include <cstdint>
#include <cstddef>

// Problem constants
#define BB 256
#define TT 2048
#define HH 512
#define MM ((size_t)BB * TT)    // 524288 rows

#define NCHK 8                  // batch chunks for stream pipelining
#define CB   (BB / NCHK)        // 32 batches per chunk
#define CTIL ((int)(MM / 128) / NCHK)  // 512 M-tiles per chunk

// ---------------------------------------------------------------------------
// g_buf (1.07 GB) split into two packed fp16 regions, NO aliasing:
//   bytes [0, MM*1024)          : h1[m][0..511] fp16, row stride 1024 B
//   bytes [MM*1024, MM*2048)    : pre2[m][0..511] fp16, row stride 1024 B
// ---------------------------------------------------------------------------
__device__ __align__(128) float  g_buf[MM * 512];
__device__ __align__(128) __half g_bh[512 * 512];

#define H1_BYTES(m)  ((char*)g_buf + (size_t)(m) * 1024)
#define C_BYTES(m)   ((char*)g_buf + MM * 1024 + (size_t)(m) * 1024)

// ===========================================================================
// helpers
// ===========================================================================
__device__ __forceinline__ uint32_t smem_u32(const void* p) {
    uint32_t a;
    asm("{ .reg .u64 t; cvta.to.shared.u64 t, %1; cvt.u32.u64 %0, t; }"
        : "=r"(a) : "l"(p));
    return a;
}
__device__ __forceinline__ void cpasync16(uint32_t dst, const void* src) {
    asm volatile("cp.async.cg.shared.global [%0], [%1], 16;"
                 :: "r"(dst), "l"(src) : "memory");
}
#define CP_COMMIT() asm volatile("cp.async.commit_group;" ::: "memory")

__device__ __forceinline__ void mma16816(float* d, const uint32_t* a,
                                         uint32_t b0, uint32_t b1) {
    asm volatile(
        "mma.sync.aligned.m16n8k16.row.col.f32.f16.f16.f32 "
        "{%0,%1,%2,%3}, {%4,%5,%6,%7}, {%8,%9}, {%0,%1,%2,%3};"
        : "+f"(d[0]), "+f"(d[1]), "+f"(d[2]), "+f"(d[3])
        : "r"(a[0]), "r"(a[1]), "r"(a[2]), "r"(a[3]), "r"(b0), "r"(b1));
}

__device__ __forceinline__ void ldsm4(uint32_t* r, uint32_t addr) {
    asm volatile("ldmatrix.sync.aligned.m8n8.x4.shared.b16 {%0,%1,%2,%3}, [%4];"
                 : "=r"(r[0]), "=r"(r[1]), "=r"(r[2]), "=r"(r[3]) : "r"(addr));
}

// ===========================================================================
// Kernel 1: pre1 + scan1 fused; writes h1 fp16 rows (1024 B packed).
// ===========================================================================
__global__ __launch_bounds__(HH) void k1_pre_scan1(
    const float* __restrict__ x, const float* __restrict__ W1,
    const float* __restrict__ u1, const float* __restrict__ b1, int b0)
{
    __shared__ float sx[2 * 512];

    const int b = b0 + blockIdx.x;
    const int h = threadIdx.x;

    const float w0 = W1[2 * h + 0];
    const float w1 = W1[2 * h + 1];
    const float u  = u1[h];
    const float bb = b1[h];

    const float* xb = x + (size_t)b * TT * 2;
    __half* rowbase = (__half*)H1_BYTES((size_t)b * TT);

    float hs = 0.0f;

    for (int t0 = 0; t0 < TT; t0 += 512) {
        __syncthreads();
        ((float2*)sx)[h] = ((const float2*)(xb + 2 * t0))[h];
        __syncthreads();

        #pragma unroll 8
        for (int tt = 0; tt < 512; tt++) {
            float x0 = sx[2 * tt + 0];
            float x1 = sx[2 * tt + 1];
            float pre = fmaf(w0, x0, fmaf(w1, x1, bb));
            hs = fmaxf(fmaf(u, hs, pre), 0.0f);
            rowbase[(size_t)(t0 + tt) * 512 + h] = __float2half(hs);
        }
    }
}

// ===========================================================================
// Kernel 1b: W2 -> fp16
// ===========================================================================
__global__ __launch_bounds__(512) void k_conv(const float* __restrict__ W2)
{
    int i = blockIdx.x * 512 + threadIdx.x;
    g_bh[i] = __float2half(W2[i]);
}

// ===========================================================================
// Kernel 2: pre2 = h1 @ W2^T, fp16 mma.sync (fp32 acc), ldmatrix.
// 2-stage cp.async pipeline, ONE __syncthreads per iteration (loads are
// issued AFTER the barrier, so the barrier alone orders iter it-1's reads of
// the buffer against iter it's overwrite).
// CTA = 128 M rows, 256 threads (8 warps, 4M x 2N), warp tile 32M x 64N.
// N in 4 chunks of 128; K in 8 chunks of 64; it = nc*8 + kt, 32 iters.
// Stage = A chunk (128 x 144 B) + B chunk (128 x 144 B) = 36864 B; 2 stages.
// ===========================================================================
#define CH_STRIDE 144
#define A_BYTES   18432
#define STG_BYTES 36864
#define K2_SMEM   73728

__global__ __launch_bounds__(256, 2) void k2_gemm_mma(int by0)
{
    extern __shared__ char dsmem[];
    const uint32_t sb = smem_u32(dsmem);

    const int tid = threadIdx.x;
    const int w   = tid >> 5;
    const int l   = tid & 31;
    const int wm  = w & 3;          // M warp (32 rows)
    const int wn  = w >> 2;         // N warp (64 cols)
    const size_t by = (size_t)(by0 + blockIdx.x);   // M tile: rows [128*by, +128)

    const char* Abase = H1_BYTES(by * 128);   // 128 rows x 1024 B

    #define LOAD_CH(it, stg) do {                                              \
        int _nc = (it) >> 3, _kt = (it) & 7;                                   \
        uint32_t _sd = sb + (stg) * STG_BYTES;                                 \
        _Pragma("unroll")                                                      \
        for (int i = 0; i < 4; i++) {                                          \
            int idx = tid + i * 256;          /* 0..1023 */                    \
            int row = idx >> 3;               /* 0..127 */                     \
            int c   = idx & 7;                /* 16B col in 128B k-chunk */    \
            cpasync16(_sd + row * CH_STRIDE + c * 16,                          \
                      Abase + (size_t)row * 1024 + _kt * 128 + c * 16);        \
            cpasync16(_sd + A_BYTES + row * CH_STRIDE + c * 16,                \
                      (const char*)g_bh + (size_t)(_nc * 128 + row) * 1024     \
                          + _kt * 128 + c * 16);                               \
        }                                                                      \
    } while (0)

    LOAD_CH(0, 0);
    CP_COMMIT();

    float acc[2][8][4];             // [mi][nh*2+jj][4]

    const int lrow = l & 15;        // ldmatrix row within 16
    const int lcol = (l >> 4) * 16; // 0 or 16 bytes (k half)

    // epilogue indices
    const int r = l >> 2;           // 0..7
    const int q = l & 3;

    __half* Cbase = (__half*)C_BYTES(by * 128);

    for (int it = 0; it < 32; it++) {
        const int st = it & 1;
        // chunk `it` is the only (or oldest) pending group: wait for it.
        asm volatile("cp.async.wait_group 0;" ::: "memory");
        __syncthreads();            // all threads done reading stage st from
                                    // iter it-2; stage st data for iter it visible

        if (it + 1 < 32) {          // prefetch next chunk into the other stage
            LOAD_CH(it + 1, st ^ 1);
            CP_COMMIT();
        }

        const int nc = it >> 3;
        const int kt = it & 7;
        if (kt == 0) {
            #pragma unroll
            for (int mi = 0; mi < 2; mi++)
                #pragma unroll
                for (int j = 0; j < 8; j++)
                    #pragma unroll
                    for (int d = 0; d < 4; d++) acc[mi][j][d] = 0.0f;
        }

        const uint32_t sd = sb + st * STG_BYTES;
        const uint32_t aB = sd + (wm * 32 + lrow) * CH_STRIDE + lcol;
        const uint32_t bB = sd + A_BYTES + (wn * 64 + lrow) * CH_STRIDE + lcol;

        #pragma unroll
        for (int ks = 0; ks < 4; ks++) {
            const int kb = ks * 32;
            uint32_t a0[4], a1[4];
            ldsm4(a0, aB + kb);
            ldsm4(a1, aB + 16 * CH_STRIDE + kb);

            #pragma unroll
            for (int nh = 0; nh < 4; nh++) {
                uint32_t bbf[4];
                ldsm4(bbf, bB + nh * (16 * CH_STRIDE) + kb);
                #pragma unroll
                for (int jj = 0; jj < 2; jj++) {
                    mma16816(acc[0][nh * 2 + jj], a0, bbf[jj], bbf[jj + 2]);
                    mma16816(acc[1][nh * 2 + jj], a1, bbf[jj], bbf[jj + 2]);
                }
            }
        }

        if (kt == 7) {
            // fp16 C write for this N chunk (separate buffer, no aliasing)
            #pragma unroll
            for (int mi = 0; mi < 2; mi++) {
                const size_t row0 = (size_t)(wm * 32 + mi * 16 + r);
                #pragma unroll
                for (int nh = 0; nh < 4; nh++) {
                    #pragma unroll
                    for (int jj = 0; jj < 2; jj++) {
                        const int col = nc * 128 + wn * 64 + nh * 16 + jj * 8 + q * 2;
                        const float* a4 = acc[mi][nh * 2 + jj];
                        __half* c0 = Cbase + row0 * 512 + col;
                        __half* c1 = Cbase + (row0 + 8) * 512 + col;
                        *(__half2*)c0 = __floats2half2_rn(a4[0], a4[1]);
                        *(__half2*)c1 = __floats2half2_rn(a4[2], a4[3]);
                    }
                }
            }
        }
    }
}

// ===========================================================================
// Kernel 3: scan2 (last state) over packed fp16 pre2, cp.async-staged.
// ===========================================================================
#define K3_CHUNK 32
#define K3_CHUNK_BYTES (K3_CHUNK * 1024)
#define K3_SMEM (2 * K3_CHUNK_BYTES)

__global__ __launch_bounds__(HH) void k3_scan2_out(
    const float* __restrict__ u2, const float* __restrict__ b2,
    const float* __restrict__ Wf, const float* __restrict__ bf,
    float* __restrict__ out, int b0)
{
    extern __shared__ char k3smem[];
    __shared__ float red[HH];

    const int b = b0 + blockIdx.x;
    const int g = threadIdx.x;
    const uint32_t sbase = smem_u32(k3smem);

    const float u  = u2[g];
    const float bb = b2[g];

    const char* base = C_BYTES((size_t)b * TT);

    #define K3_LOAD(c, buf) do {                                               \
        _Pragma("unroll")                                                      \
        for (int i = 0; i < 4; i++) {                                          \
            int idx = g + i * 512;            /* 0..2047 */                    \
            cpasync16(sbase + (buf) * K3_CHUNK_BYTES + idx * 16,               \
                      base + (size_t)(c) * K3_CHUNK_BYTES + idx * 16);         \
        }                                                                      \
    } while (0)

    float hs = 0.0f;

    K3_LOAD(0, 0);
    CP_COMMIT();

    const int NCH = TT / K3_CHUNK;   // 64
    for (int c = 0; c < NCH; c++) {
        const int buf = c & 1;
        if (c + 1 < NCH) {
            K3_LOAD(c + 1, buf ^ 1);
            CP_COMMIT();
            asm volatile("cp.async.wait_group 1;" ::: "memory");
        } else {
            asm volatile("cp.async.wait_group 0;" ::: "memory");
        }
        __syncthreads();

        const __half* sh = (const __half*)(k3smem + buf * K3_CHUNK_BYTES);
        #pragma unroll
        for (int tt = 0; tt < K3_CHUNK; tt++) {
            float v = __half2float(sh[tt * 512 + g]) + bb;
            hs = fmaxf(fmaf(u, hs, v), 0.0f);
        }
        __syncthreads();
    }

    red[g] = hs * Wf[g];
    __syncthreads();
    #pragma unroll
    for (int s = HH / 2; s > 0; s >>= 1) {
        if (g < s) red[g] += red[g + s];
        __syncthreads();
    }
    if (g == 0) out[b] = red[0] + bf[0];
}

// ===========================================================================
// launch — 3-stream chunked pipeline (8 chunks of 32 batches):
//   s0 (default): conv, k1(0..7)    [records ek1[i]]
//   s1 (low prio): k2(i) after ek1[i]   [records ek2[i]]
//   s2 (high prio): k3(i) after ek2[i]
// k1/k3 (DRAM-bound, tensor idle) overlap k2 (tensor-bound, DRAM 12%).
// ===========================================================================
extern "C" void kernel_launch(void* const* d_in, const int* in_sizes, int n_in,
                              void* d_out, int out_size)
{
    const float* x  = (const float*)d_in[0];
    const float* W1 = (const float*)d_in[1];
    const float* u1 = (const float*)d_in[2];
    const float* b1 = (const float*)d_in[3];
    const float* W2 = (const float*)d_in[4];
    const float* u2 = (const float*)d_in[5];
    const float* b2 = (const float*)d_in[6];
    const float* Wf = (const float*)d_in[7];
    const float* bf = (const float*)d_in[8];
    float* out = (float*)d_out;

    static cudaStream_t s1, s2;
    static cudaEvent_t ek1[NCHK], ek2[NCHK], eJ;
    static int inited = 0;
    if (!inited) {
        cudaFuncSetAttribute(k2_gemm_mma,
                             cudaFuncAttributeMaxDynamicSharedMemorySize, K2_SMEM);
        cudaFuncSetAttribute(k3_scan2_out,
                             cudaFuncAttributeMaxDynamicSharedMemorySize, K3_SMEM);
        int pLeast, pGreatest;
        cudaDeviceGetStreamPriorityRange(&pLeast, &pGreatest);
        cudaStreamCreateWithPriority(&s1, cudaStreamNonBlocking, pLeast);    // k2: low
        cudaStreamCreateWithPriority(&s2, cudaStreamNonBlocking, pGreatest); // k3: high
        for (int i = 0; i < NCHK; i++) {
            cudaEventCreateWithFlags(&ek1[i], cudaEventDisableTiming);
            cudaEventCreateWithFlags(&ek2[i], cudaEventDisableTiming);
        }
        cudaEventCreateWithFlags(&eJ, cudaEventDisableTiming);
        inited = 1;
    }

    // s0: conv then k1 chunks (conv precedes all k1 on s0, so ek1[i] also
    // implies conv completion for k2)
    k_conv<<<512, 512>>>(W2);
    for (int i = 0; i < NCHK; i++) {
        k1_pre_scan1<<<CB, HH>>>(x, W1, u1, b1, i * CB);
        cudaEventRecord(ek1[i], 0);
    }

    // s1: GEMM chunks
    for (int i = 0; i < NCHK; i++) {
        cudaStreamWaitEvent(s1, ek1[i], 0);
        k2_gemm_mma<<<CTIL, 256, K2_SMEM, s1>>>(i * CTIL);
        cudaEventRecord(ek2[i], s1);
    }

    // s2: scan2 chunks
    for (int i = 0; i < NCHK; i++) {
        cudaStreamWaitEvent(s2, ek2[i], 0);
        k3_scan2_out<<<CB, HH, K3_SMEM, s2>>>(u2, b2, Wf, bf, out, i * CB);
    }

    // join back to s0
    cudaEventRecord(eJ, s2);
    cudaStreamWaitEvent(0, eJ, 0);
}

// round 17
// speedup vs baseline: 1.0857x; 1.0857x over previous
#include <cuda_runtime.h>
#include <cuda_bf16.h>
#include <cuda_fp16.h>
#include <cstdint>
#include <cstddef>

// Problem constants
#define BB 256
#define TT 2048
#define HH 512
#define MM ((size_t)BB * TT)    // 524288 rows

// ---------------------------------------------------------------------------
// g_buf (1.07 GB) split into two packed fp16 regions, NO aliasing:
//   bytes [0, MM*1024)          : h1[m][0..511] fp16, row stride 1024 B
//   bytes [MM*1024, MM*2048)    : pre2[m][0..511] fp16, row stride 1024 B
// ---------------------------------------------------------------------------
__device__ __align__(128) float  g_buf[MM * 512];
__device__ __align__(128) __half g_bh[512 * 512];

#define H1_BYTES(m)  ((char*)g_buf + (size_t)(m) * 1024)
#define C_BYTES(m)   ((char*)g_buf + MM * 1024 + (size_t)(m) * 1024)

// ===========================================================================
// helpers
// ===========================================================================
__device__ __forceinline__ uint32_t smem_u32(const void* p) {
    uint32_t a;
    asm("{ .reg .u64 t; cvta.to.shared.u64 t, %1; cvt.u32.u64 %0, t; }"
        : "=r"(a) : "l"(p));
    return a;
}
__device__ __forceinline__ void cpasync16(uint32_t dst, const void* src) {
    asm volatile("cp.async.cg.shared.global [%0], [%1], 16;"
                 :: "r"(dst), "l"(src) : "memory");
}
#define CP_COMMIT() asm volatile("cp.async.commit_group;" ::: "memory")

__device__ __forceinline__ void mma16816(float* d, const uint32_t* a,
                                         uint32_t b0, uint32_t b1) {
    asm volatile(
        "mma.sync.aligned.m16n8k16.row.col.f32.f16.f16.f32 "
        "{%0,%1,%2,%3}, {%4,%5,%6,%7}, {%8,%9}, {%0,%1,%2,%3};"
        : "+f"(d[0]), "+f"(d[1]), "+f"(d[2]), "+f"(d[3])
        : "r"(a[0]), "r"(a[1]), "r"(a[2]), "r"(a[3]), "r"(b0), "r"(b1));
}

__device__ __forceinline__ void ldsm4(uint32_t* r, uint32_t addr) {
    asm volatile("ldmatrix.sync.aligned.m8n8.x4.shared.b16 {%0,%1,%2,%3}, [%4];"
                 : "=r"(r[0]), "=r"(r[1]), "=r"(r[2]), "=r"(r[3]) : "r"(addr));
}

// ===========================================================================
// Kernel 1: pre1 + scan1 fused; writes h1 fp16 rows (1024 B packed).
// Latency-floor-bound (~50us/launch) -> launch in 2 WIDE halves only.
// ===========================================================================
__global__ __launch_bounds__(HH) void k1_pre_scan1(
    const float* __restrict__ x, const float* __restrict__ W1,
    const float* __restrict__ u1, const float* __restrict__ b1, int b0)
{
    __shared__ float sx[2 * 512];

    const int b = b0 + blockIdx.x;
    const int h = threadIdx.x;

    const float w0 = W1[2 * h + 0];
    const float w1 = W1[2 * h + 1];
    const float u  = u1[h];
    const float bb = b1[h];

    const float* xb = x + (size_t)b * TT * 2;
    __half* rowbase = (__half*)H1_BYTES((size_t)b * TT);

    float hs = 0.0f;

    for (int t0 = 0; t0 < TT; t0 += 512) {
        __syncthreads();
        ((float2*)sx)[h] = ((const float2*)(xb + 2 * t0))[h];
        __syncthreads();

        #pragma unroll 8
        for (int tt = 0; tt < 512; tt++) {
            float x0 = sx[2 * tt + 0];
            float x1 = sx[2 * tt + 1];
            float pre = fmaf(w0, x0, fmaf(w1, x1, bb));
            hs = fmaxf(fmaf(u, hs, pre), 0.0f);
            rowbase[(size_t)(t0 + tt) * 512 + h] = __float2half(hs);
        }
    }
}

// ===========================================================================
// Kernel 1b: W2 -> fp16
// ===========================================================================
__global__ __launch_bounds__(512) void k_conv(const float* __restrict__ W2)
{
    int i = blockIdx.x * 512 + threadIdx.x;
    g_bh[i] = __float2half(W2[i]);
}

// ===========================================================================
// Kernel 2: pre2 = h1 @ W2^T, fp16 mma.sync (fp32 acc), ldmatrix.
// 3-stage cp.async pipeline, ONE __syncthreads per iteration (R14-proven).
// CTA = 128 M rows, 256 threads (8 warps, 4M x 2N), warp tile 32M x 64N.
// N in 4 chunks of 128; K in 8 chunks of 64; it = nc*8 + kt, 32 iters.
// Stage = A chunk (128 x 144 B) + B chunk (128 x 144 B) = 36864 B; 3 stages.
// ===========================================================================
#define CH_STRIDE 144
#define A_BYTES   18432
#define STG_BYTES 36864
#define K2_SMEM   110592

__global__ __launch_bounds__(256, 2) void k2_gemm_mma(int by0)
{
    extern __shared__ char dsmem[];
    const uint32_t sb = smem_u32(dsmem);

    const int tid = threadIdx.x;
    const int w   = tid >> 5;
    const int l   = tid & 31;
    const int wm  = w & 3;          // M warp (32 rows)
    const int wn  = w >> 2;         // N warp (64 cols)
    const size_t by = (size_t)(by0 + blockIdx.x);   // M tile: rows [128*by, +128)

    const char* Abase = H1_BYTES(by * 128);   // 128 rows x 1024 B

    #define LOAD_CH(it, stg) do {                                              \
        int _nc = (it) >> 3, _kt = (it) & 7;                                   \
        uint32_t _sd = sb + (stg) * STG_BYTES;                                 \
        _Pragma("unroll")                                                      \
        for (int i = 0; i < 4; i++) {                                          \
            int idx = tid + i * 256;          /* 0..1023 */                    \
            int row = idx >> 3;               /* 0..127 */                     \
            int c   = idx & 7;                /* 16B col in 128B k-chunk */    \
            cpasync16(_sd + row * CH_STRIDE + c * 16,                          \
                      Abase + (size_t)row * 1024 + _kt * 128 + c * 16);        \
            cpasync16(_sd + A_BYTES + row * CH_STRIDE + c * 16,                \
                      (const char*)g_bh + (size_t)(_nc * 128 + row) * 1024     \
                          + _kt * 128 + c * 16);                               \
        }                                                                      \
    } while (0)

    LOAD_CH(0, 0);
    CP_COMMIT();
    LOAD_CH(1, 1);
    CP_COMMIT();

    float acc[2][8][4];             // [mi][nh*2+jj][4]

    const int lrow = l & 15;        // ldmatrix row within 16
    const int lcol = (l >> 4) * 16; // 0 or 16 bytes (k half)

    // epilogue indices
    const int r = l >> 2;           // 0..7
    const int q = l & 3;

    __half* Cbase = (__half*)C_BYTES(by * 128);

    int st = 0;                     // compute stage
    int ld = 2;                     // load stage

    for (int it = 0; it < 32; it++) {
        if (it == 31) {
            asm volatile("cp.async.wait_group 0;" ::: "memory");
        } else {
            asm volatile("cp.async.wait_group 1;" ::: "memory");
        }
        __syncthreads();

        if (it + 2 < 32) {
            LOAD_CH(it + 2, ld);
            CP_COMMIT();
        }

        const int nc = it >> 3;
        const int kt = it & 7;
        if (kt == 0) {
            #pragma unroll
            for (int mi = 0; mi < 2; mi++)
                #pragma unroll
                for (int j = 0; j < 8; j++)
                    #pragma unroll
                    for (int d = 0; d < 4; d++) acc[mi][j][d] = 0.0f;
        }

        const uint32_t sd = sb + st * STG_BYTES;
        const uint32_t aB = sd + (wm * 32 + lrow) * CH_STRIDE + lcol;
        const uint32_t bB = sd + A_BYTES + (wn * 64 + lrow) * CH_STRIDE + lcol;

        #pragma unroll
        for (int ks = 0; ks < 4; ks++) {
            const int kb = ks * 32;
            uint32_t a0[4], a1[4];
            ldsm4(a0, aB + kb);
            ldsm4(a1, aB + 16 * CH_STRIDE + kb);

            #pragma unroll
            for (int nh = 0; nh < 4; nh++) {
                uint32_t bbf[4];
                ldsm4(bbf, bB + nh * (16 * CH_STRIDE) + kb);
                #pragma unroll
                for (int jj = 0; jj < 2; jj++) {
                    mma16816(acc[0][nh * 2 + jj], a0, bbf[jj], bbf[jj + 2]);
                    mma16816(acc[1][nh * 2 + jj], a1, bbf[jj], bbf[jj + 2]);
                }
            }
        }

        if (kt == 7) {
            // fp16 C write for this N chunk (separate buffer, no aliasing)
            #pragma unroll
            for (int mi = 0; mi < 2; mi++) {
                const size_t row0 = (size_t)(wm * 32 + mi * 16 + r);
                #pragma unroll
                for (int nh = 0; nh < 4; nh++) {
                    #pragma unroll
                    for (int jj = 0; jj < 2; jj++) {
                        const int col = nc * 128 + wn * 64 + nh * 16 + jj * 8 + q * 2;
                        const float* a4 = acc[mi][nh * 2 + jj];
                        __half* c0 = Cbase + row0 * 512 + col;
                        __half* c1 = Cbase + (row0 + 8) * 512 + col;
                        *(__half2*)c0 = __floats2half2_rn(a4[0], a4[1]);
                        *(__half2*)c1 = __floats2half2_rn(a4[2], a4[3]);
                    }
                }
            }
        }

        st = (st == 2) ? 0 : st + 1;
        ld = (ld == 2) ? 0 : ld + 1;
    }
}

// ===========================================================================
// Kernel 3: scan2 (last state) over packed fp16 pre2, cp.async-staged.
// BW-bound -> safe to chunk (each chunk still saturates DRAM).
// ===========================================================================
#define K3_CHUNK 32
#define K3_CHUNK_BYTES (K3_CHUNK * 1024)
#define K3_SMEM (2 * K3_CHUNK_BYTES)

__global__ __launch_bounds__(HH) void k3_scan2_out(
    const float* __restrict__ u2, const float* __restrict__ b2,
    const float* __restrict__ Wf, const float* __restrict__ bf,
    float* __restrict__ out, int b0)
{
    extern __shared__ char k3smem[];
    __shared__ float red[HH];

    const int b = b0 + blockIdx.x;
    const int g = threadIdx.x;
    const uint32_t sbase = smem_u32(k3smem);

    const float u  = u2[g];
    const float bb = b2[g];

    const char* base = C_BYTES((size_t)b * TT);

    #define K3_LOAD(c, buf) do {                                               \
        _Pragma("unroll")                                                      \
        for (int i = 0; i < 4; i++) {                                          \
            int idx = g + i * 512;            /* 0..2047 */                    \
            cpasync16(sbase + (buf) * K3_CHUNK_BYTES + idx * 16,               \
                      base + (size_t)(c) * K3_CHUNK_BYTES + idx * 16);         \
        }                                                                      \
    } while (0)

    float hs = 0.0f;

    K3_LOAD(0, 0);
    CP_COMMIT();

    const int NCH = TT / K3_CHUNK;   // 64
    for (int c = 0; c < NCH; c++) {
        const int buf = c & 1;
        if (c + 1 < NCH) {
            K3_LOAD(c + 1, buf ^ 1);
            CP_COMMIT();
            asm volatile("cp.async.wait_group 1;" ::: "memory");
        } else {
            asm volatile("cp.async.wait_group 0;" ::: "memory");
        }
        __syncthreads();

        const __half* sh = (const __half*)(k3smem + buf * K3_CHUNK_BYTES);
        #pragma unroll
        for (int tt = 0; tt < K3_CHUNK; tt++) {
            float v = __half2float(sh[tt * 512 + g]) + bb;
            hs = fmaxf(fmaf(u, hs, v), 0.0f);
        }
        __syncthreads();
    }

    red[g] = hs * Wf[g];
    __syncthreads();
    #pragma unroll
    for (int s = HH / 2; s > 0; s >>= 1) {
        if (g < s) red[g] += red[g + s];
        __syncthreads();
    }
    if (g == 0) out[b] = red[0] + bf[0];
}

// ===========================================================================
// launch — k1 in 2 WIDE halves (latency-bound); k2 in 4 chunks; k3 in 4
// chunks on a high-priority stream overlapping the next k2 chunk.
//   s0: conv, k1a, [e1a], k1b, [e1b]          (k1b overlaps k2c0)
//   s1 (low prio):  e1a -> k2c0,k2c1 ; e1b -> k2c2,k2c3   [g_i after each]
//   s2 (high prio): g_i -> k3 chunk i   (chunks 0-2 hidden under k2)
// ===========================================================================
extern "C" void kernel_launch(void* const* d_in, const int* in_sizes, int n_in,
                              void* d_out, int out_size)
{
    const float* x  = (const float*)d_in[0];
    const float* W1 = (const float*)d_in[1];
    const float* u1 = (const float*)d_in[2];
    const float* b1 = (const float*)d_in[3];
    const float* W2 = (const float*)d_in[4];
    const float* u2 = (const float*)d_in[5];
    const float* b2 = (const float*)d_in[6];
    const float* Wf = (const float*)d_in[7];
    const float* bf = (const float*)d_in[8];
    float* out = (float*)d_out;

    static cudaStream_t s1, s2;
    static cudaEvent_t e1a, e1b, g_ev[4], eJ;
    static int inited = 0;
    if (!inited) {
        cudaFuncSetAttribute(k2_gemm_mma,
                             cudaFuncAttributeMaxDynamicSharedMemorySize, K2_SMEM);
        cudaFuncSetAttribute(k3_scan2_out,
                             cudaFuncAttributeMaxDynamicSharedMemorySize, K3_SMEM);
        int pLeast, pGreatest;
        cudaDeviceGetStreamPriorityRange(&pLeast, &pGreatest);
        cudaStreamCreateWithPriority(&s1, cudaStreamNonBlocking, pLeast);    // k2: low
        cudaStreamCreateWithPriority(&s2, cudaStreamNonBlocking, pGreatest); // k3: high
        cudaEventCreateWithFlags(&e1a, cudaEventDisableTiming);
        cudaEventCreateWithFlags(&e1b, cudaEventDisableTiming);
        for (int i = 0; i < 4; i++)
            cudaEventCreateWithFlags(&g_ev[i], cudaEventDisableTiming);
        cudaEventCreateWithFlags(&eJ, cudaEventDisableTiming);
        inited = 1;
    }

    const int HB    = BB / 2;               // 128 batches per k1 half
    const int QTIL  = (int)(MM / 128) / 4;  // 1024 M-tiles per k2 chunk
    const int QB    = BB / 4;               // 64 batches per k3 chunk

    // s0: conv + k1 halves (conv precedes k1a, so e1a implies conv done)
    k_conv<<<512, 512>>>(W2);
    k1_pre_scan1<<<HB, HH>>>(x, W1, u1, b1, 0);
    cudaEventRecord(e1a, 0);
    k1_pre_scan1<<<HB, HH>>>(x, W1, u1, b1, HB);   // overlaps k2c0 on s1
    cudaEventRecord(e1b, 0);

    // s1: k2 chunks (0,1 gated on e1a; 2,3 on e1b)
    cudaStreamWaitEvent(s1, e1a, 0);
    k2_gemm_mma<<<QTIL, 256, K2_SMEM, s1>>>(0 * QTIL);
    cudaEventRecord(g_ev[0], s1);
    k2_gemm_mma<<<QTIL, 256, K2_SMEM, s1>>>(1 * QTIL);
    cudaEventRecord(g_ev[1], s1);
    cudaStreamWaitEvent(s1, e1b, 0);
    k2_gemm_mma<<<QTIL, 256, K2_SMEM, s1>>>(2 * QTIL);
    cudaEventRecord(g_ev[2], s1);
    k2_gemm_mma<<<QTIL, 256, K2_SMEM, s1>>>(3 * QTIL);
    cudaEventRecord(g_ev[3], s1);

    // s2: k3 chunks, each gated on its k2 chunk; chunks 0-2 overlap k2 1-3
    for (int i = 0; i < 4; i++) {
        cudaStreamWaitEvent(s2, g_ev[i], 0);
        k3_scan2_out<<<QB, HH, K3_SMEM, s2>>>(u2, b2, Wf, bf, out, i * QB);
    }

    // join back to s0
    cudaEventRecord(eJ, s2);
    cudaStreamWaitEvent(0, eJ, 0);
}